// round 6
// baseline (speedup 1.0000x reference)
#include <cuda_runtime.h>
#include <math_constants.h>

// ScalarDistanceDeepSet via exact piecewise-linear collapse + cell histogram.
// 4 kernels: setup (tables + bucket-less prep + zero), hist (bucket-accelerated
// boundary search + integer atomics), pooled (per-(batch,segment) warp scans +
// range algebra -> fixed-point atomics), head (small MLP).
// All cross-block accumulation is integer => deterministic.

#define NB    32
#define NN    256
#define P1    64
#define P2    128
#define R1    256
#define R2    128
#define OD    64
#define NSEG  65
#define NCELL 129
#define NSLOT (NSEG * NCELL)      // 8385
#define NBND  (NSLOT - 1)         // 8384
#define SCALE_F    67108864.0f    // 2^26
#define INV_SCALE  (1.0 / 67108864.0)
#define PSCALE     4194304.0      // 2^22
#define INV_PSCALE (1.0 / 4194304.0)
#define HIST_GRID 592
#define NTASK (NB * (NN / 4))     // 2048
#define NBUCK 4096
#define BLO   (-6.0f)
#define BSTEP (12.0f / 4096.0f)
#define BINV  (4096.0f / 12.0f)

__device__ float     g_bnd[NBND];
__device__ float     g_A[NSEG * P2];
__device__ float     g_Cc[NSEG * P2];
__device__ int2      g_range[NSEG * P2];
__device__ long long g_hs[NB * NSLOT];
__device__ int       g_hc[NB * NSLOT];
__device__ long long g_poolq[NB * P2];

// ---------------------------------------------------------------------------
// Setup: blocks 0..64 build tables for segment m=blockIdx.x (local redundant
// rank computation); all blocks also zero the histograms + pooled accumulators.
// ---------------------------------------------------------------------------
__global__ void __launch_bounds__(256)
setup_kernel(const float* __restrict__ W1, const float* __restrict__ b1,
             const float* __restrict__ W2, const float* __restrict__ b2,
             int nb) {
    __shared__ float sw[P1], sbb[P1], stk[P1], sts[P1], sth[P2];
    __shared__ int   srk[P1];
    int tid = threadIdx.x;

    {   // zero (all blocks)
        int stride = nb * 256, idx0 = blockIdx.x * 256 + tid;
        for (int i = idx0; i < NB * NSLOT; i += stride) g_hs[i] = 0;
        for (int i = idx0; i < NB * NSLOT; i += stride) g_hc[i] = 0;
        for (int i = idx0; i < NB * P2;   i += stride) g_poolq[i] = 0;
    }

    int m = blockIdx.x;
    if (m >= NSEG) return;

    if (tid < P1) {
        float w = W1[tid], b = b1[tid];
        sw[tid] = w; sbb[tid] = b;
        stk[tid] = (w != 0.0f) ? (-b / w) : CUDART_INF_F;
    }
    __syncthreads();
    if (tid < P1) {
        float tkv = stk[tid];
        int r = 0;
        for (int kk = 0; kk < P1; kk++) {
            float tv = stk[kk];
            if (tv < tkv || (tv == tkv && kk < tid)) r++;
        }
        srk[tid] = r;
        sts[r] = tkv;
    }
    __syncthreads();
    if (tid < P2) {
        float a = 0.0f, c = b2[tid];
        for (int k = 0; k < P1; k++) {
            float w = sw[k], b = sbb[k];
            int r = srk[k];
            bool active = (w > 0.0f) ? (m > r)
                        : (w < 0.0f) ? (m <= r)
                        : (b > 0.0f);
            if (active) {
                float w2 = W2[k * P2 + tid];
                a = fmaf(w, w2, a);
                c = fmaf(b, w2, c);
            }
        }
        int idx = m * P2 + tid;
        g_A[idx] = a; g_Cc[idx] = c;

        float lo_t = (m == 0)        ? -CUDART_INF_F : sts[m - 1];
        float hi_t = (m == NSEG - 1) ?  CUDART_INF_F : sts[m];
        float th;
        if (a != 0.0f) th = fminf(fmaxf(-c / a, lo_t), hi_t);
        else           th = lo_t;
        sth[tid] = th;
    }
    __syncthreads();
    if (tid < P2) {
        int idx = m * P2 + tid;
        float a = g_A[idx], c = g_Cc[idx];
        float th = sth[tid];
        int p = 0;
        for (int k = 0; k < P2; k++) {
            float tv = sth[k];
            if (tv < th || (tv == th && k < tid)) p++;
        }
        g_bnd[m * NCELL + p] = th;
        if (tid == 0 && m < NSEG - 1) g_bnd[m * NCELL + P2] = sts[m];
        int rlo, rhi;
        if (a > 0.0f)      { rlo = p + 1; rhi = NCELL; }
        else if (a < 0.0f) { rlo = 0;     rhi = p + 1; }
        else               { rlo = 0;     rhi = (c > 0.0f) ? NCELL : 0; }
        g_range[idx] = make_int2(rlo, rhi);
    }
}

// ---------------------------------------------------------------------------
// Histogram with uniform-bucket acceleration. Per block: stage sorted
// boundaries + build bstart[k] = count(bnd < BLO + k*BSTEP). Per pair:
// bucket -> narrow range -> short ballot-terminated branchless search.
// ---------------------------------------------------------------------------
__global__ void __launch_bounds__(256)
hist_kernel(const float* __restrict__ dm, const int* __restrict__ lengths) {
    __shared__ float sb[NBND];            // 33.5 KB
    __shared__ int   bstart[NBUCK + 1];   // 16.4 KB
    int tid = threadIdx.x;
    for (int i = tid; i < NBND; i += 256) sb[i] = g_bnd[i];
    __syncthreads();
    // build bucket index: 17 searches per thread, independent (ILP-hidden)
    for (int k = tid; k <= NBUCK; k += 256) {
        float edge = fmaf((float)k, BSTEP, BLO);
        int pos = 0, n = NBND;
        while (n > 0) {
            int half = n >> 1, mid = pos + half;
            if (sb[mid] < edge) { pos = mid + 1; n -= half + 1; }
            else                { n = half; }
        }
        bstart[k] = pos;
    }
    __syncthreads();

    for (int task = blockIdx.x; task < NTASK; task += gridDim.x) {
        int b  = task & 31;
        int i0 = (task >> 5) << 2;
        int L  = __ldg(lengths + b);
        if (i0 >= L - 1) continue;

        const float* rowp = dm + ((size_t)b << 16) + ((size_t)i0 << 8) + tid;
        float s[4]; int n[4], pos[4];
        #pragma unroll
        for (int r = 0; r < 4; r++) {
            int i = i0 + r;
            bool valid = (i < L - 1) && (tid > i) && (tid < L);
            float sv = valid ? rowp[r << 8] : 0.0f;
            s[r] = sv;
            int ib = (int)floorf((sv - BLO) * BINV);
            int lo_r = (ib <= 0) ? 0 : bstart[min(ib - 1, NBUCK)];
            int hi_r = (ib >= NBUCK - 1) ? NBND : bstart[ib + 2];
            pos[r] = lo_r;
            n[r]   = valid ? (hi_r - lo_r) : 0;
        }
        for (;;) {
            int alive = (n[0] | n[1] | n[2] | n[3]);
            if (!__ballot_sync(0xffffffffu, alive != 0)) break;
            #pragma unroll
            for (int r = 0; r < 4; r++) {
                if (n[r] > 0) {
                    int half = n[r] >> 1;
                    int mid  = pos[r] + half;
                    if (sb[mid] < s[r]) { pos[r] = mid + 1; n[r] -= half + 1; }
                    else                { n[r] = half; }
                }
            }
        }
        unsigned long long* hsb = (unsigned long long*)g_hs + (size_t)b * NSLOT;
        int* hcb = g_hc + (size_t)b * NSLOT;
        #pragma unroll
        for (int r = 0; r < 4; r++) {
            int i = i0 + r;
            bool valid = (i < L - 1) && (tid > i) && (tid < L);
            if (valid) {
                long long q = llrintf(s[r] * SCALE_F);
                atomicAdd(&hsb[pos[r]], (unsigned long long)q);
                atomicAdd(&hcb[pos[r]], 1);
            }
        }
    }
}

// ---------------------------------------------------------------------------
// Pooled: 1 warp per (batch, segment) unit. 129-cell scan via shuffles, range
// algebra for 128 features, fixed-point atomic accumulate into g_poolq.
// ---------------------------------------------------------------------------
#define POOL_WARPS 4
__global__ void __launch_bounds__(POOL_WARPS * 32)
pooled_kernel() {
    __shared__ long long ps[POOL_WARPS][130];
    __shared__ int       pc[POOL_WARPS][130];
    int tid = threadIdx.x, warp = tid >> 5, lane = tid & 31;
    int u = blockIdx.x * POOL_WARPS + warp;
    if (u >= NSEG * NB) return;
    int m = u % NSEG;
    int b = u / NSEG;

    const long long* hs = g_hs + (size_t)b * NSLOT + m * NCELL;
    const int*       hc = g_hc + (size_t)b * NSLOT + m * NCELL;
    int base = lane * 4;
    int ncl  = (lane == 31) ? 5 : 4;
    long long ls[5]; int lc[5];
    long long runS = 0; int runC = 0;
    #pragma unroll
    for (int e = 0; e < 5; e++) {
        if (e < ncl) {
            ls[e] = runS; lc[e] = runC;
            runS += __ldcg(hs + base + e);
            runC += __ldcg(hc + base + e);
        }
    }
    long long incS = runS; int incC = runC;
    #pragma unroll
    for (int off = 1; off < 32; off <<= 1) {
        long long vS = __shfl_up_sync(0xffffffffu, incS, off);
        int       vC = __shfl_up_sync(0xffffffffu, incC, off);
        if (lane >= off) { incS += vS; incC += vC; }
    }
    long long exS = incS - runS; int exC = incC - runC;
    #pragma unroll
    for (int e = 0; e < 5; e++) {
        if (e < ncl) {
            ps[warp][base + e] = exS + ls[e];
            pc[warp][base + e] = exC + lc[e];
        }
    }
    if (lane == 31) { ps[warp][NCELL] = incS; pc[warp][NCELL] = incC; }
    __syncwarp();

    #pragma unroll
    for (int ff = 0; ff < 4; ff++) {
        int f = lane + 32 * ff;
        int idx = m * P2 + f;
        float a = g_A[idx], c = g_Cc[idx];
        int2 rg = g_range[idx];
        long long ds = ps[warp][rg.y] - ps[warp][rg.x];
        int       dc = pc[warp][rg.y] - pc[warp][rg.x];
        float val = a * (float)((double)ds * INV_SCALE) + c * (float)dc;
        long long q = llrint((double)val * PSCALE);
        atomicAdd((unsigned long long*)&g_poolq[b * P2 + f],
                  (unsigned long long)q);
    }
}

// ---------------------------------------------------------------------------
// Head: grid NB, 256 threads. pooled from fixed-point, then 128->256->128->64.
// ---------------------------------------------------------------------------
__global__ void __launch_bounds__(256)
head_kernel(const float* __restrict__ W3, const float* __restrict__ b3,
            const float* __restrict__ W4, const float* __restrict__ b4,
            const float* __restrict__ W5, const float* __restrict__ b5,
            float* __restrict__ out) {
    __shared__ float pooled[P2];
    __shared__ float r1v[R1];
    __shared__ float r2v[R2];
    __shared__ float part[256];
    int b = blockIdx.x, tid = threadIdx.x;

    if (tid < P2)
        pooled[tid] = (float)((double)__ldcg(&g_poolq[b * P2 + tid]) * INV_PSCALE);
    __syncthreads();
    {   // layer1: 256 outputs, K=128
        float v = b3[tid];
        #pragma unroll 16
        for (int k = 0; k < P2; k++)
            v = fmaf(pooled[k], W3[k * R1 + tid], v);
        r1v[tid] = fmaxf(v, 0.0f);
    }
    __syncthreads();
    {   // layer2: 128 outputs, 2-way K split (K=256)
        int o = tid & 127, ch = tid >> 7;
        float v = 0.0f;
        int k0 = ch * 128;
        #pragma unroll 16
        for (int k = 0; k < 128; k++)
            v = fmaf(r1v[k0 + k], W4[(k0 + k) * R2 + o], v);
        part[tid] = v;
    }
    __syncthreads();
    if (tid < R2)
        r2v[tid] = fmaxf(b4[tid] + part[tid] + part[tid + 128], 0.0f);
    __syncthreads();
    {   // layer3: 64 outputs, 4-way K split (K=128)
        int o = tid & 63, ch = tid >> 6;
        float v = 0.0f;
        int k0 = ch * 32;
        #pragma unroll
        for (int k = 0; k < 32; k++)
            v = fmaf(r2v[k0 + k], W5[(k0 + k) * OD + o], v);
        __syncthreads();
        part[tid] = v;
    }
    __syncthreads();
    if (tid < OD) {
        out[b * OD + tid] = b5[tid] + part[tid] + part[tid + 64]
                          + part[tid + 128] + part[tid + 192];
    }
}

// ---------------------------------------------------------------------------
extern "C" void kernel_launch(void* const* d_in, const int* in_sizes, int n_in,
                              void* d_out, int out_size) {
    const float* dm      = (const float*)d_in[0];
    const int*   lengths = (const int*)  d_in[1];
    const float* W1 = (const float*)d_in[2],  *b1 = (const float*)d_in[3];
    const float* W2 = (const float*)d_in[4],  *b2 = (const float*)d_in[5];
    const float* W3 = (const float*)d_in[6],  *b3 = (const float*)d_in[7];
    const float* W4 = (const float*)d_in[8],  *b4 = (const float*)d_in[9];
    const float* W5 = (const float*)d_in[10], *b5 = (const float*)d_in[11];
    float* out = (float*)d_out;

    const int pool_grid = (NSEG * NB + POOL_WARPS - 1) / POOL_WARPS;  // 520

    setup_kernel<<<297, 256>>>(W1, b1, W2, b2, 297);
    hist_kernel<<<HIST_GRID, 256>>>(dm, lengths);
    pooled_kernel<<<pool_grid, POOL_WARPS * 32>>>();
    head_kernel<<<NB, 256>>>(W3, b3, W4, b4, W5, b5, out);
}

// round 8
// speedup vs baseline: 1.1815x; 1.1815x over previous
#include <cuda_runtime.h>
#include <math_constants.h>

// ScalarDistanceDeepSet via exact piecewise-linear collapse + cell histogram.
// K1: per-segment tables + zero hists + warm head weights into L2.
// K2 (fused): 16 blocks per batch do the pair->cell histogram (branchless
// 14-step ILP-4 search + integer atomics); the LAST block to finish a batch
// (monotonic counter) does that batch's per-segment warp scans + range algebra
// + head MLP, alone and in fixed order => deterministic.

#define NB    32
#define NN    256
#define P1    64
#define P2    128
#define R1    256
#define R2    128
#define OD    64
#define NSEG  65
#define NCELL 129
#define NSLOT (NSEG * NCELL)      // 8385
#define NBND  (NSLOT - 1)         // 8384
#define SCALE_F    67108864.0f    // 2^26
#define INV_SCALE  (1.0 / 67108864.0)
#define KPB   16                  // hist blocks per batch

__device__ float        g_bnd[NBND];
__device__ float        g_A[NSEG * P2];
__device__ float        g_Cc[NSEG * P2];
__device__ int2         g_range[NSEG * P2];
__device__ long long    g_hs[NB * NSLOT];
__device__ int          g_hc[NB * NSLOT];
__device__ unsigned int g_done[NB];    // monotonic, no reset needed
__device__ float        g_sink[256];   // L2-warm sink

// ---------------------------------------------------------------------------
// K1: blocks 0..64 build tables for segment m (block-local ranks); all blocks
// zero the histograms; blocks >=65 stream head weights to warm L2.
// ---------------------------------------------------------------------------
__global__ void __launch_bounds__(256)
setup_kernel(const float* __restrict__ W1, const float* __restrict__ b1,
             const float* __restrict__ W2, const float* __restrict__ b2,
             const float* __restrict__ W3, const float* __restrict__ W4,
             const float* __restrict__ W5, int nb) {
    __shared__ float sw[P1], sbb[P1], stk[P1], sts[P1], sth[P2];
    __shared__ int   srk[P1];
    int tid = threadIdx.x;

    {   // zero (all blocks)
        int stride = nb * 256, idx0 = blockIdx.x * 256 + tid;
        for (int i = idx0; i < NB * NSLOT; i += stride) g_hs[i] = 0;
        for (int i = idx0; i < NB * NSLOT; i += stride) g_hc[i] = 0;
    }

    int m = blockIdx.x;
    if (m >= NSEG) {
        // warm W3/W4/W5 into L2 (head reads them later)
        float acc = 0.0f;
        int idx0 = (blockIdx.x - NSEG) * 256 + tid;
        int stride = (nb - NSEG) * 256;
        for (int i = idx0; i < P2 * R1; i += stride) acc += W3[i];
        for (int i = idx0; i < R1 * R2; i += stride) acc += W4[i];
        for (int i = idx0; i < R2 * OD; i += stride) acc += W5[i];
        if (tid == 0) g_sink[blockIdx.x - NSEG] = acc;
        return;
    }

    if (tid < P1) {
        float w = W1[tid], b = b1[tid];
        sw[tid] = w; sbb[tid] = b;
        stk[tid] = (w != 0.0f) ? (-b / w) : CUDART_INF_F;
    }
    __syncthreads();
    if (tid < P1) {
        float tkv = stk[tid];
        int r = 0;
        for (int kk = 0; kk < P1; kk++) {
            float tv = stk[kk];
            if (tv < tkv || (tv == tkv && kk < tid)) r++;
        }
        srk[tid] = r;
        sts[r] = tkv;
    }
    __syncthreads();
    if (tid < P2) {
        float a = 0.0f, c = b2[tid];
        for (int k = 0; k < P1; k++) {
            float w = sw[k], b = sbb[k];
            int r = srk[k];
            bool active = (w > 0.0f) ? (m > r)
                        : (w < 0.0f) ? (m <= r)
                        : (b > 0.0f);
            if (active) {
                float w2 = W2[k * P2 + tid];
                a = fmaf(w, w2, a);
                c = fmaf(b, w2, c);
            }
        }
        int idx = m * P2 + tid;
        g_A[idx] = a; g_Cc[idx] = c;

        float lo_t = (m == 0)        ? -CUDART_INF_F : sts[m - 1];
        float hi_t = (m == NSEG - 1) ?  CUDART_INF_F : sts[m];
        float th;
        if (a != 0.0f) th = fminf(fmaxf(-c / a, lo_t), hi_t);
        else           th = lo_t;
        sth[tid] = th;
    }
    __syncthreads();
    if (tid < P2) {
        int idx = m * P2 + tid;
        float a = g_A[idx], c = g_Cc[idx];
        float th = sth[tid];
        int p = 0;
        for (int k = 0; k < P2; k++) {
            float tv = sth[k];
            if (tv < th || (tv == th && k < tid)) p++;
        }
        g_bnd[m * NCELL + p] = th;
        if (tid == 0 && m < NSEG - 1) g_bnd[m * NCELL + P2] = sts[m];
        int rlo, rhi;
        if (a > 0.0f)      { rlo = p + 1; rhi = NCELL; }
        else if (a < 0.0f) { rlo = 0;     rhi = p + 1; }
        else               { rlo = 0;     rhi = (c > 0.0f) ? NCELL : 0; }
        g_range[idx] = make_int2(rlo, rhi);
    }
}

// ---------------------------------------------------------------------------
// K2: fused hist + (last block per batch) pooled scans + head MLP.
// ---------------------------------------------------------------------------
union SmU {
    float sb[NBND];                                              // 33.5 KB
    struct { long long ps[8][130]; int pc[8][130];
             float fpart[8][P2]; } pool;                         // 16.6 KB
    struct { float pooled[P2]; float r1[R1]; float r2[R2];
             float part[256]; } hd;                              // 3 KB
};

__global__ void __launch_bounds__(256)
fused_kernel(const float* __restrict__ dm, const int* __restrict__ lengths,
             const float* __restrict__ W3, const float* __restrict__ b3,
             const float* __restrict__ W4, const float* __restrict__ b4,
             const float* __restrict__ W5, const float* __restrict__ b5,
             float* __restrict__ out) {
    __shared__ SmU sm;
    __shared__ int islast;
    int tid = threadIdx.x;
    int kb  = blockIdx.x;      // 0..15  hist sub-block within batch
    int b   = blockIdx.y;      // batch

    // ---- hist phase ----
    for (int i = tid; i < NBND; i += 256) sm.sb[i] = g_bnd[i];
    __syncthreads();

    int L = __ldg(lengths + b);
    unsigned long long* hsb = (unsigned long long*)g_hs + (size_t)b * NSLOT;
    int* hcb = g_hc + (size_t)b * NSLOT;

    for (int t4 = kb; t4 < NN / 4; t4 += KPB) {
        int i0 = t4 << 2;
        if (i0 >= L - 1) continue;
        const float* rowp = dm + ((size_t)b << 16) + ((size_t)i0 << 8) + tid;
        float s[4]; int n[4], pos[4];
        #pragma unroll
        for (int r = 0; r < 4; r++) {
            int i = i0 + r;
            bool valid = (i < L - 1) && (tid > i) && (tid < L);
            s[r]   = valid ? rowp[r << 8] : 0.0f;
            pos[r] = 0;
            n[r]   = valid ? NBND : 0;
        }
        #pragma unroll
        for (int it = 0; it < 14; it++) {
            #pragma unroll
            for (int r = 0; r < 4; r++) {
                if (n[r] > 0) {
                    int half = n[r] >> 1;
                    int mid  = pos[r] + half;
                    if (sm.sb[mid] < s[r]) { pos[r] = mid + 1; n[r] -= half + 1; }
                    else                   { n[r] = half; }
                }
            }
        }
        #pragma unroll
        for (int r = 0; r < 4; r++) {
            int i = i0 + r;
            bool valid = (i < L - 1) && (tid > i) && (tid < L);
            if (valid) {
                long long q = llrintf(s[r] * SCALE_F);
                atomicAdd(&hsb[pos[r]], (unsigned long long)q);
                atomicAdd(&hcb[pos[r]], 1);
            }
        }
    }

    // ---- last-arriver election ----
    __threadfence();
    __syncthreads();
    if (tid == 0) {
        unsigned int old = atomicAdd(&g_done[b], 1u);
        islast = ((old & (KPB - 1)) == KPB - 1) ? 1 : 0;
    }
    __syncthreads();
    if (!islast) return;
    __threadfence();

    // ---- pooled phase (this block only; fixed order => deterministic) ----
    int warp = tid >> 5, lane = tid & 31;
    float accf[4] = {0.0f, 0.0f, 0.0f, 0.0f};
    for (int m = warp; m < NSEG; m += 8) {
        const long long* hs = g_hs + (size_t)b * NSLOT + m * NCELL;
        const int*       hc = g_hc + (size_t)b * NSLOT + m * NCELL;
        int base = lane * 4;
        int ncl  = (lane == 31) ? 5 : 4;
        long long ls[5]; int lc[5];
        long long runS = 0; int runC = 0;
        #pragma unroll
        for (int e = 0; e < 5; e++) {
            if (e < ncl) {
                ls[e] = runS; lc[e] = runC;
                runS += __ldcg(hs + base + e);
                runC += __ldcg(hc + base + e);
            }
        }
        long long incS = runS; int incC = runC;
        #pragma unroll
        for (int off = 1; off < 32; off <<= 1) {
            long long vS = __shfl_up_sync(0xffffffffu, incS, off);
            int       vC = __shfl_up_sync(0xffffffffu, incC, off);
            if (lane >= off) { incS += vS; incC += vC; }
        }
        long long exS = incS - runS; int exC = incC - runC;
        #pragma unroll
        for (int e = 0; e < 5; e++) {
            if (e < ncl) {
                sm.pool.ps[warp][base + e] = exS + ls[e];
                sm.pool.pc[warp][base + e] = exC + lc[e];
            }
        }
        if (lane == 31) { sm.pool.ps[warp][NCELL] = incS; sm.pool.pc[warp][NCELL] = incC; }
        __syncwarp();

        #pragma unroll
        for (int ff = 0; ff < 4; ff++) {
            int f = lane + 32 * ff;
            int idx = m * P2 + f;
            float a = g_A[idx], c = g_Cc[idx];
            int2 rg = g_range[idx];
            long long ds = sm.pool.ps[warp][rg.y] - sm.pool.ps[warp][rg.x];
            int       dc = sm.pool.pc[warp][rg.y] - sm.pool.pc[warp][rg.x];
            accf[ff] += a * (float)((double)ds * INV_SCALE) + c * (float)dc;
        }
        __syncwarp();
    }
    #pragma unroll
    for (int ff = 0; ff < 4; ff++)
        sm.pool.fpart[warp][lane + 32 * ff] = accf[ff];
    __syncthreads();

    float poolv = 0.0f;
    if (tid < P2) {
        #pragma unroll
        for (int w = 0; w < 8; w++) poolv += sm.pool.fpart[w][tid];
    }
    __syncthreads();           // pool arrays dead; reuse union for head
    if (tid < P2) sm.hd.pooled[tid] = poolv;
    __syncthreads();

    // ---- head phase (R6-proven reduction pattern, race-free) ----
    {   // layer1: 256 outputs, K=128
        float v = b3[tid];
        #pragma unroll 32
        for (int k = 0; k < P2; k++)
            v = fmaf(sm.hd.pooled[k], W3[k * R1 + tid], v);
        sm.hd.r1[tid] = fmaxf(v, 0.0f);
    }
    __syncthreads();
    {   // layer2: 128 outputs, 2-way K split (K=256)
        int o = tid & 127, ch = tid >> 7;
        float v = 0.0f;
        int k0 = ch * 128;
        #pragma unroll 32
        for (int k = 0; k < 128; k++)
            v = fmaf(sm.hd.r1[k0 + k], W4[(k0 + k) * R2 + o], v);
        sm.hd.part[tid] = v;
    }
    __syncthreads();
    if (tid < R2)
        sm.hd.r2[tid] = fmaxf(b4[tid] + sm.hd.part[tid] + sm.hd.part[tid + 128], 0.0f);
    __syncthreads();
    {   // layer3: 64 outputs, 4-way K split (K=128)
        int o = tid & 63, ch = tid >> 6;
        float v = 0.0f;
        int k0 = ch * 32;
        #pragma unroll
        for (int k = 0; k < 32; k++)
            v = fmaf(sm.hd.r2[k0 + k], W5[(k0 + k) * OD + o], v);
        __syncthreads();
        sm.hd.part[tid] = v;
    }
    __syncthreads();
    if (tid < OD) {
        out[b * OD + tid] = b5[tid] + sm.hd.part[tid] + sm.hd.part[tid + 64]
                          + sm.hd.part[tid + 128] + sm.hd.part[tid + 192];
    }
}

// ---------------------------------------------------------------------------
extern "C" void kernel_launch(void* const* d_in, const int* in_sizes, int n_in,
                              void* d_out, int out_size) {
    const float* dm      = (const float*)d_in[0];
    const int*   lengths = (const int*)  d_in[1];
    const float* W1 = (const float*)d_in[2],  *b1 = (const float*)d_in[3];
    const float* W2 = (const float*)d_in[4],  *b2 = (const float*)d_in[5];
    const float* W3 = (const float*)d_in[6],  *b3 = (const float*)d_in[7];
    const float* W4 = (const float*)d_in[8],  *b4 = (const float*)d_in[9];
    const float* W5 = (const float*)d_in[10], *b5 = (const float*)d_in[11];
    float* out = (float*)d_out;

    setup_kernel<<<160, 256>>>(W1, b1, W2, b2, W3, W4, W5, 160);
    fused_kernel<<<dim3(KPB, NB), 256>>>(dm, lengths, W3, b3, W4, b4, W5, b5, out);
}

// round 9
// speedup vs baseline: 1.8383x; 1.5560x over previous
#include <cuda_runtime.h>
#include <math_constants.h>

// ScalarDistanceDeepSet via exact piecewise-linear collapse + cell histogram.
// Pipeline: setup (tables + zero + L2-warm head weights), dedupe (unique
// boundary values + rank map + bucket index, single block), hist (bucketed
// short search over uniques -> original rank -> ONE packed 64-bit atomic),
// pooled (warp per (batch,segment): packed scan + range algebra -> fixed-point
// atomics), head (512-thread MLP). All cross-block accumulation is integer.

#define NB    32
#define NN    256
#define P1    64
#define P2    128
#define R1    256
#define R2    128
#define OD    64
#define NSEG  65
#define NCELL 129
#define NSLOT (NSEG * NCELL)      // 8385
#define NBND  (NSLOT - 1)         // 8384
#define SCALE_F    67108864.0f    // 2^26
#define INV_SCALE  (1.0 / 67108864.0)
#define PSCALE     4194304.0      // 2^22
#define INV_PSCALE (1.0 / 4194304.0)
#define QBIAS      (1LL << 29)
#define PACK_ONE   (1ULL << 48)
#define LOWMASK    ((1ULL << 48) - 1ULL)
#define NBUCK 1024
#define BLO   (-6.0f)
#define BSTEP (12.0f / 1024.0f)
#define BINV  (1024.0f / 12.0f)
#define HIST_GRID 592
#define NTASK (NB * (NN / 4))     // 2048
#define POOL_WARPS 4

__device__ float              g_bnd[NBND];
__device__ float              g_A[NSEG * P2];
__device__ float              g_Cc[NSEG * P2];
__device__ int2               g_range[NSEG * P2];
__device__ float              g_uv[NBND];           // unique sorted boundaries
__device__ unsigned short     g_pref[NBND + 1];     // first-occurrence rank
__device__ int                g_bstart[NBUCK + 1];  // count(uv < edge_k)
__device__ int                g_U;
__device__ int                g_maxw;
__device__ unsigned long long g_h[NB * NSLOT];      // packed (cnt<<48 | q+bias)
__device__ unsigned long long g_poolq[NB * P2];     // fixed-point pooled
__device__ float              g_sink[256];

// ---------------------------------------------------------------------------
// Setup: blocks 0..64 build tables for segment m (block-local ranks); all
// blocks zero the packed hist + pooled; blocks >=65 warm head weights into L2.
// ---------------------------------------------------------------------------
__global__ void __launch_bounds__(256)
setup_kernel(const float* __restrict__ W1, const float* __restrict__ b1,
             const float* __restrict__ W2, const float* __restrict__ b2,
             const float* __restrict__ W3, const float* __restrict__ W4,
             const float* __restrict__ W5, int nb) {
    __shared__ float sw[P1], sbb[P1], stk[P1], sts[P1], sth[P2];
    __shared__ int   srk[P1];
    int tid = threadIdx.x;

    {   // zero (all blocks)
        int stride = nb * 256, idx0 = blockIdx.x * 256 + tid;
        for (int i = idx0; i < NB * NSLOT; i += stride) g_h[i] = 0ULL;
        for (int i = idx0; i < NB * P2;   i += stride) g_poolq[i] = 0ULL;
    }

    int m = blockIdx.x;
    if (m >= NSEG) {
        float acc = 0.0f;
        int idx0 = (blockIdx.x - NSEG) * 256 + tid;
        int stride = (nb - NSEG) * 256;
        for (int i = idx0; i < P2 * R1; i += stride) acc += W3[i];
        for (int i = idx0; i < R1 * R2; i += stride) acc += W4[i];
        for (int i = idx0; i < R2 * OD; i += stride) acc += W5[i];
        if (tid == 0) g_sink[blockIdx.x - NSEG] = acc;
        return;
    }

    if (tid < P1) {
        float w = W1[tid], b = b1[tid];
        sw[tid] = w; sbb[tid] = b;
        stk[tid] = (w != 0.0f) ? (-b / w) : CUDART_INF_F;
    }
    __syncthreads();
    if (tid < P1) {
        float tkv = stk[tid];
        int r = 0;
        for (int kk = 0; kk < P1; kk++) {
            float tv = stk[kk];
            if (tv < tkv || (tv == tkv && kk < tid)) r++;
        }
        srk[tid] = r;
        sts[r] = tkv;
    }
    __syncthreads();
    if (tid < P2) {
        float a = 0.0f, c = b2[tid];
        for (int k = 0; k < P1; k++) {
            float w = sw[k], b = sbb[k];
            int r = srk[k];
            bool active = (w > 0.0f) ? (m > r)
                        : (w < 0.0f) ? (m <= r)
                        : (b > 0.0f);
            if (active) {
                float w2 = W2[k * P2 + tid];
                a = fmaf(w, w2, a);
                c = fmaf(b, w2, c);
            }
        }
        int idx = m * P2 + tid;
        g_A[idx] = a; g_Cc[idx] = c;

        float lo_t = (m == 0)        ? -CUDART_INF_F : sts[m - 1];
        float hi_t = (m == NSEG - 1) ?  CUDART_INF_F : sts[m];
        float th;
        if (a != 0.0f) th = fminf(fmaxf(-c / a, lo_t), hi_t);
        else           th = lo_t;
        sth[tid] = th;
    }
    __syncthreads();
    if (tid < P2) {
        int idx = m * P2 + tid;
        float a = g_A[idx], c = g_Cc[idx];
        float th = sth[tid];
        int p = 0;
        for (int k = 0; k < P2; k++) {
            float tv = sth[k];
            if (tv < th || (tv == th && k < tid)) p++;
        }
        g_bnd[m * NCELL + p] = th;
        if (tid == 0 && m < NSEG - 1) g_bnd[m * NCELL + P2] = sts[m];
        int rlo, rhi;
        if (a > 0.0f)      { rlo = p + 1; rhi = NCELL; }
        else if (a < 0.0f) { rlo = 0;     rhi = p + 1; }
        else               { rlo = 0;     rhi = (c > 0.0f) ? NCELL : 0; }
        g_range[idx] = make_int2(rlo, rhi);
    }
}

// ---------------------------------------------------------------------------
// Dedupe: single block. g_bnd is globally sorted by construction; mark heads,
// block scan -> unique array uv + first-occurrence ranks pref, then bucket
// table bstart and the widened max bucket width (uniform search step count).
// ---------------------------------------------------------------------------
#define DCH 9   // 1024*9 >= 8384
__global__ void __launch_bounds__(1024)
dedupe_kernel() {
    __shared__ int sc[1024];
    int t = threadIdx.x;
    int i0 = t * DCH;
    int heads[DCH]; int cnt = 0;
    #pragma unroll
    for (int e = 0; e < DCH; e++) {
        int i = i0 + e; int h = 0;
        if (i < NBND) h = (i == 0) || (g_bnd[i] != g_bnd[i - 1]);
        heads[e] = h; cnt += h;
    }
    sc[t] = cnt; __syncthreads();
    for (int off = 1; off < 1024; off <<= 1) {
        int v = sc[t]; if (t >= off) v += sc[t - off];
        __syncthreads(); sc[t] = v; __syncthreads();
    }
    int excl = sc[t] - cnt;
    int U = sc[1023];
    int u = excl;
    #pragma unroll
    for (int e = 0; e < DCH; e++) {
        int i = i0 + e;
        if (heads[e]) { g_uv[u] = g_bnd[i]; g_pref[u] = (unsigned short)i; u++; }
    }
    if (t == 0) { g_pref[U] = (unsigned short)NBND; g_U = U; }
    __threadfence();
    __syncthreads();

    // bucket table: bstart[k] = count(uv < BLO + k*BSTEP)
    for (int k = t; k <= NBUCK; k += 1024) {
        float edge = fmaf((float)k, BSTEP, BLO);
        int pos = 0, n = U;
        while (n > 0) {
            int half = n >> 1, mid = pos + half;
            if (g_uv[mid] < edge) { pos = mid + 1; n -= half + 1; }
            else                  { n = half; }
        }
        g_bstart[k] = pos;
    }
    __threadfence();
    __syncthreads();

    // widened max bucket width (must match hist's lo/hi formula exactly)
    int lmax = 0;
    for (int k = t; k < NBUCK; k += 1024) {
        int lo = (k == 0)         ? 0 : g_bstart[k - 1];
        int hi = (k >= NBUCK - 1) ? U : g_bstart[k + 2];
        lmax = max(lmax, hi - lo);
    }
    sc[t] = lmax; __syncthreads();
    for (int off = 512; off > 0; off >>= 1) {
        if (t < off) sc[t] = max(sc[t], sc[t + off]);
        __syncthreads();
    }
    if (t == 0) g_maxw = sc[0];
}

// ---------------------------------------------------------------------------
// Histogram: per pair, bucket -> short uniform-step branchless search over
// uniques (ILP-4 across rows) -> original rank via pref -> one packed atomic.
// ---------------------------------------------------------------------------
#define HIST_SMEM (NBND * 4 + (NBND + 2) * 2 + (NBUCK + 1) * 4)   // 54408 B

__global__ void __launch_bounds__(256)
hist_kernel(const float* __restrict__ dm, const int* __restrict__ lengths) {
    extern __shared__ char dyn[];
    float*          suv   = (float*)dyn;                               // [U]
    unsigned short* spref = (unsigned short*)(dyn + NBND * 4);         // [U+1]
    int*            sbst  = (int*)(dyn + NBND * 4 + (NBND + 2) * 2);   // [NBUCK+1]
    int tid = threadIdx.x;

    int U    = g_U;
    int maxw = g_maxw;
    int steps = (maxw > 0) ? (32 - __clz(maxw)) : 0;   // block-uniform

    for (int i = tid; i < U;       i += 256) suv[i]   = g_uv[i];
    for (int i = tid; i <= U;      i += 256) spref[i] = g_pref[i];
    for (int i = tid; i <= NBUCK;  i += 256) sbst[i]  = g_bstart[i];
    __syncthreads();

    for (int task = blockIdx.x; task < NTASK; task += gridDim.x) {
        int b  = task & 31;
        int i0 = (task >> 5) << 2;
        int L  = __ldg(lengths + b);
        if (i0 >= L - 1) continue;

        const float* rowp = dm + ((size_t)b << 16) + ((size_t)i0 << 8) + tid;
        float s[4]; int n[4], pos[4];
        #pragma unroll
        for (int r = 0; r < 4; r++) {
            int i = i0 + r;
            bool valid = (i < L - 1) && (tid > i) && (tid < L);
            float sv = valid ? rowp[r << 8] : 0.0f;
            s[r] = sv;
            int ib = __float2int_rd((sv - BLO) * BINV);
            ib = min(max(ib, 0), NBUCK - 1);
            int lo = (ib == 0)         ? 0 : sbst[ib - 1];
            int hi = (ib >= NBUCK - 1) ? U : sbst[ib + 2];
            pos[r] = lo;
            n[r]   = valid ? (hi - lo) : 0;
        }
        for (int it = 0; it < steps; it++) {
            #pragma unroll
            for (int r = 0; r < 4; r++) {
                if (n[r] > 0) {
                    int half = n[r] >> 1;
                    int mid  = pos[r] + half;
                    if (suv[mid] < s[r]) { pos[r] = mid + 1; n[r] -= half + 1; }
                    else                 { n[r] = half; }
                }
            }
        }
        unsigned long long* hb = g_h + (size_t)b * NSLOT;
        #pragma unroll
        for (int r = 0; r < 4; r++) {
            int i = i0 + r;
            bool valid = (i < L - 1) && (tid > i) && (tid < L);
            if (valid) {
                int pO = spref[pos[r]];
                long long q = (long long)llrintf(s[r] * SCALE_F) + QBIAS;
                atomicAdd(&hb[pO], PACK_ONE + (unsigned long long)q);
            }
        }
    }
}

// ---------------------------------------------------------------------------
// Pooled: 1 warp per (batch, segment). Packed 129-cell scan via shuffles,
// range algebra for 128 features, fixed-point atomic accumulate into g_poolq.
// ---------------------------------------------------------------------------
__global__ void __launch_bounds__(POOL_WARPS * 32)
pooled_kernel() {
    __shared__ unsigned long long ps[POOL_WARPS][130];
    int tid = threadIdx.x, warp = tid >> 5, lane = tid & 31;
    int u = blockIdx.x * POOL_WARPS + warp;
    if (u >= NSEG * NB) return;
    int m = u % NSEG;
    int b = u / NSEG;

    const unsigned long long* h = g_h + (size_t)b * NSLOT + m * NCELL;
    int base = lane * 4;
    int ncl  = (lane == 31) ? 5 : 4;
    unsigned long long ls[5];
    unsigned long long run = 0ULL;
    #pragma unroll
    for (int e = 0; e < 5; e++) {
        if (e < ncl) {
            ls[e] = run;
            run += __ldcg(h + base + e);
        }
    }
    unsigned long long inc = run;
    #pragma unroll
    for (int off = 1; off < 32; off <<= 1) {
        unsigned long long v = __shfl_up_sync(0xffffffffu, inc, off);
        if (lane >= off) inc += v;
    }
    unsigned long long ex = inc - run;
    #pragma unroll
    for (int e = 0; e < 5; e++) {
        if (e < ncl) ps[warp][base + e] = ex + ls[e];
    }
    if (lane == 31) ps[warp][NCELL] = inc;
    __syncwarp();

    #pragma unroll
    for (int ff = 0; ff < 4; ff++) {
        int f = lane + 32 * ff;
        int idx = m * P2 + f;
        float a = g_A[idx], c = g_Cc[idx];
        int2 rg = g_range[idx];
        unsigned long long dv = ps[warp][rg.y] - ps[warp][rg.x];
        int cnt = (int)(dv >> 48);
        long long sumq = (long long)(dv & LOWMASK) - ((long long)cnt << 29);
        float val = a * (float)((double)sumq * INV_SCALE) + c * (float)cnt;
        long long qq = llrint((double)val * PSCALE);
        atomicAdd(&g_poolq[b * P2 + f], (unsigned long long)qq);
    }
}

// ---------------------------------------------------------------------------
// Head: grid NB, 512 threads (R4-proven). pooled from fixed-point accumulator.
// ---------------------------------------------------------------------------
__global__ void __launch_bounds__(512)
head_kernel(const float* __restrict__ W3, const float* __restrict__ b3,
            const float* __restrict__ W4, const float* __restrict__ b4,
            const float* __restrict__ W5, const float* __restrict__ b5,
            float* __restrict__ out) {
    __shared__ float pooled[P2];
    __shared__ float r1v[R1];
    __shared__ float r2v[R2];
    __shared__ float part[512];
    int b = blockIdx.x, t = threadIdx.x;

    if (t < P2)
        pooled[t] = (float)((double)(long long)g_poolq[b * P2 + t] * INV_PSCALE);
    __syncthreads();

    {   // layer1: 256 outputs, 2-way K split (K=128)
        int o = t & 255, h = t >> 8;
        float v = 0.0f;
        int k0 = h * 64;
        #pragma unroll
        for (int k = 0; k < 64; k++)
            v = fmaf(pooled[k0 + k], W3[(k0 + k) * R1 + o], v);
        part[t] = v;
    }
    __syncthreads();
    if (t < R1)
        r1v[t] = fmaxf(b3[t] + part[t] + part[t + 256], 0.0f);
    __syncthreads();

    {   // layer2: 128 outputs, 4-way K split (K=256)
        int o = t & 127, ch = t >> 7;
        float v = 0.0f;
        int k0 = ch * 64;
        #pragma unroll
        for (int k = 0; k < 64; k++)
            v = fmaf(r1v[k0 + k], W4[(k0 + k) * R2 + o], v);
        __syncthreads();
        part[t] = v;
    }
    __syncthreads();
    if (t < R2) {
        float v = b4[t];
        #pragma unroll
        for (int j = 0; j < 4; j++) v += part[t + 128 * j];
        r2v[t] = fmaxf(v, 0.0f);
    }
    __syncthreads();

    {   // layer3: 64 outputs, 8-way K split (K=128)
        int o = t & 63, ch = t >> 6;
        float v = 0.0f;
        int k0 = ch * 16;
        #pragma unroll
        for (int k = 0; k < 16; k++)
            v = fmaf(r2v[k0 + k], W5[(k0 + k) * OD + o], v);
        __syncthreads();
        part[t] = v;
    }
    __syncthreads();
    if (t < OD) {
        float v = b5[t];
        #pragma unroll
        for (int j = 0; j < 8; j++) v += part[t + 64 * j];
        out[b * OD + t] = v;
    }
}

// ---------------------------------------------------------------------------
extern "C" void kernel_launch(void* const* d_in, const int* in_sizes, int n_in,
                              void* d_out, int out_size) {
    const float* dm      = (const float*)d_in[0];
    const int*   lengths = (const int*)  d_in[1];
    const float* W1 = (const float*)d_in[2],  *b1 = (const float*)d_in[3];
    const float* W2 = (const float*)d_in[4],  *b2 = (const float*)d_in[5];
    const float* W3 = (const float*)d_in[6],  *b3 = (const float*)d_in[7];
    const float* W4 = (const float*)d_in[8],  *b4 = (const float*)d_in[9];
    const float* W5 = (const float*)d_in[10], *b5 = (const float*)d_in[11];
    float* out = (float*)d_out;

    cudaFuncSetAttribute((const void*)hist_kernel,
                         cudaFuncAttributeMaxDynamicSharedMemorySize, HIST_SMEM);

    const int pool_grid = (NSEG * NB + POOL_WARPS - 1) / POOL_WARPS;  // 520

    setup_kernel<<<160, 256>>>(W1, b1, W2, b2, W3, W4, W5, 160);
    dedupe_kernel<<<1, 1024>>>();
    hist_kernel<<<HIST_GRID, 256, HIST_SMEM>>>(dm, lengths);
    pooled_kernel<<<pool_grid, POOL_WARPS * 32>>>();
    head_kernel<<<NB, 512>>>(W3, b3, W4, b4, W5, b5, out);
}